// round 2
// baseline (speedup 1.0000x reference)
#include <cuda_runtime.h>
#include <cuda_bf16.h>
#include <cstdint>

#define NN 10000
#define EE 40000
#define GG 128
#define NF 92
#define EF 50
#define HH 64
#define NHD 10
#define GD 108
#define LL 5
#define FPH 640   // NH*H

// ---------------- device scratch (static, no runtime alloc) ----------------
__device__ float g_h[NN * HH];
__device__ float g_init[NN * HH];
__device__ float g_ea[EE * HH];
__device__ float g_Hn[NN * FPH];     // h @ W[:64]   (25.6 MB)
__device__ float g_agg[NN * HH];
__device__ float g_score[NN];
__device__ float g_smax[GG];
__device__ float g_den[GG];
__device__ float g_pool[GG * HH];

__device__ __forceinline__ float lrelu(float v) { return v > 0.f ? v : 0.2f * v; }

__device__ __forceinline__ float warp_sum(float v) {
    v += __shfl_down_sync(0xffffffffu, v, 16);
    v += __shfl_down_sync(0xffffffffu, v, 8);
    v += __shfl_down_sync(0xffffffffu, v, 4);
    v += __shfl_down_sync(0xffffffffu, v, 2);
    v += __shfl_down_sync(0xffffffffu, v, 1);
    return v;
}

__device__ __forceinline__ void atomicMaxFloat(float* addr, float val) {
    int* ai = (int*)addr;
    int old = *ai;
    while (__int_as_float(old) < val) {
        int assumed = old;
        old = atomicCAS(ai, assumed, __float_as_int(val));
        if (old == assumed) break;
    }
}

// ---- packed f32x2 helpers (sm_103a FFMA2 path) ----
__device__ __forceinline__ unsigned long long pk2(float lo, float hi) {
    unsigned long long r;
    asm("mov.b64 %0, {%1, %2};" : "=l"(r) : "f"(lo), "f"(hi));
    return r;
}
__device__ __forceinline__ unsigned long long ffma2(unsigned long long a,
                                                    unsigned long long b,
                                                    unsigned long long c) {
    unsigned long long d;
    asm("fma.rn.f32x2 %0, %1, %2, %3;" : "=l"(d) : "l"(a), "l"(b), "l"(c));
    return d;
}
__device__ __forceinline__ float2 upk2(unsigned long long v) {
    float2 f;
    asm("mov.b64 {%0, %1}, %2;" : "=f"(f.x), "=f"(f.y) : "l"(v));
    return f;
}

// ---------------- embeddings ----------------
__global__ void embed_node_kernel(const float* __restrict__ x,
                                  const float* __restrict__ W,
                                  const float* __restrict__ b) {
    int n = blockIdx.x;
    int t = threadIdx.x;
    __shared__ float xs[NF];
    for (int k = t; k < NF; k += 64) xs[k] = x[n * NF + k];
    __syncthreads();
    float acc = b[t];
    #pragma unroll 4
    for (int k = 0; k < NF; k++) acc = fmaf(xs[k], W[k * HH + t], acc);
    float v = lrelu(acc);
    g_h[n * HH + t] = v;
    g_init[n * HH + t] = v;
}

__global__ void embed_edge_kernel(const float* __restrict__ ea,
                                  const float* __restrict__ W,
                                  const float* __restrict__ b) {
    int e = blockIdx.x;
    int t = threadIdx.x;
    __shared__ float xs[EF];
    if (t < EF) xs[t] = ea[e * EF + t];
    __syncthreads();
    float acc = b[t];
    #pragma unroll 5
    for (int k = 0; k < EF; k++) acc = fmaf(xs[k], W[k * HH + t], acc);
    g_ea[e * HH + t] = lrelu(acc);
}

__global__ void init_misc_kernel() {
    int idx = blockIdx.x * 256 + threadIdx.x;
    if (idx < NN * HH) g_agg[idx] = 0.f;
    if (idx < GG * HH) g_pool[idx] = 0.f;
    if (idx < GG) { g_smax[idx] = -3.0e38f; g_den[idx] = 0.f; }
}

// ---------------- Hn GEMM: g_Hn[N,640] = g_h[N,64] @ W[64,640] (f32x2) -------
__global__ void gemm_Hn_kernel(const float* __restrict__ W) {
    __shared__ float Ast[64][68];   // [k][m] transposed, padded (272B rows, 16B-aligned)
    __shared__ float Bs[64][68];    // [k][n]
    int bm = blockIdx.x * 64;
    int bn = blockIdx.y * 64;
    int tid = threadIdx.x;

    {   // load A transposed: thread -> (m = tid>>2, k block = (tid&3)*16)
        int e = tid >> 2, kc = (tid & 3) * 16;
        int m = bm + e;
        #pragma unroll
        for (int j = 0; j < 4; j++) {
            float4 v = make_float4(0.f, 0.f, 0.f, 0.f);
            if (m < NN) v = *(const float4*)&g_h[m * 64 + kc + 4 * j];
            Ast[kc + 4 * j + 0][e] = v.x;
            Ast[kc + 4 * j + 1][e] = v.y;
            Ast[kc + 4 * j + 2][e] = v.z;
            Ast[kc + 4 * j + 3][e] = v.w;
        }
        // load B rows
        int r = tid >> 2, cc = (tid & 3) * 16;
        #pragma unroll
        for (int j = 0; j < 4; j++) {
            float4 v = *(const float4*)&W[r * FPH + bn + cc + 4 * j];
            *(float4*)&Bs[r][cc + 4 * j] = v;
        }
    }
    __syncthreads();

    int tx = tid & 15, ty = tid >> 4;
    unsigned long long acc[4][2] = {};
    #pragma unroll 8
    for (int k = 0; k < 64; k++) {
        float4 av = *(const float4*)&Ast[k][ty * 4];
        float4 bv = *(const float4*)&Bs[k][tx * 4];
        unsigned long long b0 = pk2(bv.x, bv.y);
        unsigned long long b1 = pk2(bv.z, bv.w);
        float a_[4] = {av.x, av.y, av.z, av.w};
        #pragma unroll
        for (int i = 0; i < 4; i++) {
            unsigned long long ai = pk2(a_[i], a_[i]);
            acc[i][0] = ffma2(ai, b0, acc[i][0]);
            acc[i][1] = ffma2(ai, b1, acc[i][1]);
        }
    }
    #pragma unroll
    for (int i = 0; i < 4; i++) {
        int m = bm + ty * 4 + i;
        if (m < NN) {
            float2 p0 = upk2(acc[i][0]);
            float2 p1 = upk2(acc[i][1]);
            float4 o = make_float4(p0.x, p0.y, p1.x, p1.y);
            *(float4*)&g_Hn[(size_t)m * FPH + bn + tx * 4] = o;
        }
    }
}

// ---------------- fused layer kernel -----------------------------------------
// 64 edges per block. For each 128-col (2-head) phase:
//   P = ea_tile @ W2_chunk  (register-tiled, f32x2)
//   hi/hj = lrelu(Hn[row/col] + P) ; hj -> smem ; attention partials -> sAp
// Then per-edge softmax over heads, then msg scatter (atomicAdd).
struct FusedSM {
    float Ast[64][68];     // ea tile, [k][e]
    float Ws[64][132];     // W chunk, [k][c] (528B rows, 16B-aligned)
    float sHj[64 * FPH];   // hj, [e][c]  (160KB)
    float sAp[64 * NHD];
    float sAlpha[64 * NHD];
    float satt[NHD * 128];
    int   rows[64];
    int   cols[64];
};

__global__ void fused_layer_kernel(const float* __restrict__ W2,
                                   const float* __restrict__ att,
                                   const float* __restrict__ gamma,
                                   const float* __restrict__ beta,
                                   const int* __restrict__ ei) {
    extern __shared__ char smraw[];
    FusedSM* s = (FusedSM*)smraw;
    const float inv_std = 0.99999500003749969f; // 1/sqrt(1+1e-5)

    int tid = threadIdx.x;
    int e0 = blockIdx.x * 64;

    // block-start loads
    if (tid < 64) s->rows[tid] = ei[e0 + tid];
    else if (tid < 128) s->cols[tid - 64] = ei[EE + e0 + (tid - 64)];
    for (int idx = tid; idx < NHD * 128; idx += 256) s->satt[idx] = att[idx];
    {   // ea tile transposed
        int e = tid >> 2, kc = (tid & 3) * 16;
        #pragma unroll
        for (int j = 0; j < 4; j++) {
            float4 v = *(const float4*)&g_ea[(size_t)(e0 + e) * 64 + kc + 4 * j];
            s->Ast[kc + 4 * j + 0][e] = v.x;
            s->Ast[kc + 4 * j + 1][e] = v.y;
            s->Ast[kc + 4 * j + 2][e] = v.z;
            s->Ast[kc + 4 * j + 3][e] = v.w;
        }
    }

    int tx = tid & 15;       // col group: cols c0 = col0 + tx*8
    int ty = tid >> 4;       // edge group: edges ty*4 .. ty*4+3

    for (int ph = 0; ph < 5; ph++) {
        int col0 = ph * 128;
        __syncthreads();   // protect Ws from previous phase readers / first-iter loads
        {   // load W chunk: row r = tid>>2, cols (tid&3)*32 .. +31
            int r = tid >> 2, cseg = (tid & 3) * 32;
            #pragma unroll
            for (int j = 0; j < 8; j++) {
                float4 v = *(const float4*)&W2[(size_t)r * FPH + col0 + cseg + 4 * j];
                *(float4*)&s->Ws[r][cseg + 4 * j] = v;
            }
        }
        __syncthreads();

        // GEMM: 4 edges x 8 cols per thread
        unsigned long long acc[4][4] = {};
        #pragma unroll 8
        for (int k = 0; k < 64; k++) {
            float4 av = *(const float4*)&s->Ast[k][ty * 4];
            float4 b0 = *(const float4*)&s->Ws[k][tx * 8];
            float4 b1 = *(const float4*)&s->Ws[k][tx * 8 + 4];
            unsigned long long bp[4] = {pk2(b0.x, b0.y), pk2(b0.z, b0.w),
                                        pk2(b1.x, b1.y), pk2(b1.z, b1.w)};
            float a_[4] = {av.x, av.y, av.z, av.w};
            #pragma unroll
            for (int i = 0; i < 4; i++) {
                unsigned long long ai = pk2(a_[i], a_[i]);
                #pragma unroll
                for (int j = 0; j < 4; j++) acc[i][j] = ffma2(ai, bp[j], acc[i][j]);
            }
        }

        // epilogue: gather Hn, hi/hj, store hj, attention partials
        int hd = 2 * ph + (tx >> 3);          // head of this thread's 8 cols
        int chead = (tx * 8) & 63;            // col offset within head
        const float* attp = s->satt + hd * 128 + chead;
        float api[4];
        #pragma unroll
        for (int i = 0; i < 4; i++) {
            int e = ty * 4 + i;
            int r = s->rows[e], c = s->cols[e];
            const float* hrp = g_Hn + (size_t)r * FPH + col0 + tx * 8;
            const float* hcp = g_Hn + (size_t)c * FPH + col0 + tx * 8;
            float4 hr0 = *(const float4*)(hrp);
            float4 hr1 = *(const float4*)(hrp + 4);
            float4 hc0 = *(const float4*)(hcp);
            float4 hc1 = *(const float4*)(hcp + 4);
            float p[8], hrv[8], hcv[8];
            #pragma unroll
            for (int j = 0; j < 4; j++) {
                float2 pj = upk2(acc[i][j]);
                p[2 * j] = pj.x; p[2 * j + 1] = pj.y;
            }
            hrv[0] = hr0.x; hrv[1] = hr0.y; hrv[2] = hr0.z; hrv[3] = hr0.w;
            hrv[4] = hr1.x; hrv[5] = hr1.y; hrv[6] = hr1.z; hrv[7] = hr1.w;
            hcv[0] = hc0.x; hcv[1] = hc0.y; hcv[2] = hc0.z; hcv[3] = hc0.w;
            hcv[4] = hc1.x; hcv[5] = hc1.y; hcv[6] = hc1.z; hcv[7] = hc1.w;
            float hj[8];
            float ap = 0.f;
            #pragma unroll
            for (int m = 0; m < 8; m++) {
                float hi = lrelu(hrv[m] + p[m]);
                hj[m] = lrelu(hcv[m] + p[m]);
                ap = fmaf(hi, attp[m], ap);
                ap = fmaf(hj[m], attp[64 + m], ap);
            }
            float4 o0 = make_float4(hj[0], hj[1], hj[2], hj[3]);
            float4 o1 = make_float4(hj[4], hj[5], hj[6], hj[7]);
            *(float4*)&s->sHj[e * FPH + col0 + tx * 8] = o0;
            *(float4*)&s->sHj[e * FPH + col0 + tx * 8 + 4] = o1;
            api[i] = ap;
        }
        // reduce over the 8 col-threads of this head (tx%8 group, within warp)
        #pragma unroll
        for (int off = 4; off > 0; off >>= 1) {
            #pragma unroll
            for (int i = 0; i < 4; i++)
                api[i] += __shfl_down_sync(0xffffffffu, api[i], off, 8);
        }
        if ((tx & 7) == 0) {
            #pragma unroll
            for (int i = 0; i < 4; i++) s->sAp[(ty * 4 + i) * NHD + hd] = api[i];
        }
    }

    __syncthreads();
    // per-edge softmax over heads
    if (tid < 64) {
        float a[NHD];
        float mx = -3.0e38f;
        #pragma unroll
        for (int nh = 0; nh < NHD; nh++) {
            float v = s->sAp[tid * NHD + nh];
            v = lrelu(v);
            v = fmaf(v * inv_std, gamma[nh], beta[nh]);
            a[nh] = v;
            mx = fmaxf(mx, v);
        }
        float ssum = 0.f;
        #pragma unroll
        for (int nh = 0; nh < NHD; nh++) { a[nh] = __expf(a[nh] - mx); ssum += a[nh]; }
        float inv = 0.1f / ssum;  // fold mean-over-heads
        #pragma unroll
        for (int nh = 0; nh < NHD; nh++) s->sAlpha[tid * NHD + nh] = a[nh] * inv;
    }
    __syncthreads();

    // scatter: msg[e][t] = sum_nh alpha * hj ; atomicAdd into g_agg[row][t]
    {
        int grp = tid >> 6;        // 4 edge-lanes
        int t = tid & 63;
        for (int es = grp; es < 64; es += 4) {
            const float* hjp = s->sHj + es * FPH + t;
            const float* alp = s->sAlpha + es * NHD;
            float m = 0.f;
            #pragma unroll
            for (int nh = 0; nh < NHD; nh++) m = fmaf(alp[nh], hjp[nh * 64], m);
            atomicAdd(&g_agg[s->rows[es] * HH + t], m);
        }
    }
}

// ---------------- node update ----------------
__global__ void node_update_kernel(const float* __restrict__ b, int flags) {
    int idx = blockIdx.x * 256 + threadIdx.x;
    if (idx >= NN * HH) return;
    int t = idx & 63;
    float v = g_agg[idx] + b[t];
    if (flags & 1) v += g_h[idx];
    if (flags & 2) v += g_init[idx];
    g_h[idx] = v;
    g_agg[idx] = 0.f;
}

// ---------------- readout ----------------
__global__ void score_kernel(const int* __restrict__ batch,
                             const float* __restrict__ gfeat,
                             const float* __restrict__ W1,
                             const float* __restrict__ b1,
                             const float* __restrict__ W2,
                             const float* __restrict__ b2) {
    int n = blockIdx.x;
    int t = threadIdx.x;
    __shared__ float cat_s[HH + GD];
    __shared__ float wr[2];
    int bidx = batch[n];
    cat_s[t] = g_h[n * HH + t];
    for (int k = t; k < GD; k += 64) cat_s[HH + k] = gfeat[bidx * GD + k];
    __syncthreads();
    float acc = b1[t];
    #pragma unroll 4
    for (int k = 0; k < HH + GD; k++) acc = fmaf(cat_s[k], W1[k * HH + t], acc);
    float sv = lrelu(acc);
    float v = warp_sum(sv * W2[t]);
    if ((t & 31) == 0) wr[t >> 5] = v;
    __syncthreads();
    if (t == 0) g_score[n] = wr[0] + wr[1] + b2[0];
}

__global__ void smax_kernel(const int* __restrict__ batch) {
    int n = blockIdx.x * 256 + threadIdx.x;
    if (n >= NN) return;
    atomicMaxFloat(&g_smax[batch[n]], g_score[n]);
}

__global__ void expden_kernel(const int* __restrict__ batch) {
    int n = blockIdx.x * 256 + threadIdx.x;
    if (n >= NN) return;
    int b = batch[n];
    float ex = __expf(g_score[n] - g_smax[b]);
    g_score[n] = ex;
    atomicAdd(&g_den[b], ex);
}

__global__ void pool_kernel(const int* __restrict__ batch) {
    int n = blockIdx.x;
    int t = threadIdx.x;
    int b = batch[n];
    float w = g_score[n] / g_den[b];
    atomicAdd(&g_pool[b * HH + t], g_h[n * HH + t] * w);
}

__global__ void out_kernel(const float* __restrict__ W1,
                           const float* __restrict__ b1,
                           const float* __restrict__ W2,
                           const float* __restrict__ b2,
                           float* __restrict__ out) {
    int g = blockIdx.x;
    int t = threadIdx.x;
    __shared__ float ps[HH];
    __shared__ float wr[2];
    ps[t] = g_pool[g * HH + t];
    __syncthreads();
    float acc = b1[t];
    #pragma unroll 4
    for (int k = 0; k < HH; k++) acc = fmaf(ps[k], W1[k * HH + t], acc);
    float r = fmaxf(acc, 0.f);
    float v = warp_sum(r * W2[t]);
    if ((t & 31) == 0) wr[t >> 5] = v;
    __syncthreads();
    if (t == 0) out[g] = wr[0] + wr[1] + b2[0];
}

// ---------------- launch ----------------
extern "C" void kernel_launch(void* const* d_in, const int* in_sizes, int n_in,
                              void* d_out, int out_size) {
    const float* x        = (const float*)d_in[0];
    const int*   ei       = (const int*)  d_in[1];
    const float* eattr    = (const float*)d_in[2];
    const int*   batch    = (const int*)  d_in[3];
    const float* gfeat    = (const float*)d_in[4];
    const float* node_W   = (const float*)d_in[5];
    const float* node_b   = (const float*)d_in[6];
    const float* edge_W   = (const float*)d_in[7];
    const float* edge_b   = (const float*)d_in[8];
    const float* conv_W   = (const float*)d_in[9];
    const float* conv_att = (const float*)d_in[10];
    const float* conv_b   = (const float*)d_in[11];
    const float* conv_g   = (const float*)d_in[12];
    const float* conv_be  = (const float*)d_in[13];
    const float* ga_W1    = (const float*)d_in[14];
    const float* ga_b1    = (const float*)d_in[15];
    const float* ga_W2    = (const float*)d_in[16];
    const float* ga_b2    = (const float*)d_in[17];
    const float* out_W1   = (const float*)d_in[18];
    const float* out_b1   = (const float*)d_in[19];
    const float* out_W2   = (const float*)d_in[20];
    const float* out_b2   = (const float*)d_in[21];
    float* out = (float*)d_out;

    cudaFuncSetAttribute(fused_layer_kernel,
                         cudaFuncAttributeMaxDynamicSharedMemorySize,
                         (int)sizeof(FusedSM));

    embed_node_kernel<<<NN, 64>>>(x, node_W, node_b);
    embed_edge_kernel<<<EE, 64>>>(eattr, edge_W, edge_b);
    init_misc_kernel<<<(NN * HH + 255) / 256, 256>>>();

    for (int i = 0; i < LL; i++) {
        const float* Wi = conv_W + (size_t)i * 2 * HH * FPH;
        gemm_Hn_kernel<<<dim3((NN + 63) / 64, FPH / 64), 256>>>(Wi);
        fused_layer_kernel<<<EE / 64, 256, sizeof(FusedSM)>>>(
            Wi + (size_t)HH * FPH,
            conv_att + (size_t)i * NHD * 2 * HH,
            conv_g + i * NHD, conv_be + i * NHD, ei);
        int flags = (i > 0 ? 1 : 0) | (i == LL - 1 ? 2 : 0);
        node_update_kernel<<<(NN * HH + 255) / 256, 256>>>(conv_b + i * HH, flags);
    }

    score_kernel<<<NN, 64>>>(batch, gfeat, ga_W1, ga_b1, ga_W2, ga_b2);
    smax_kernel<<<(NN + 255) / 256, 256>>>(batch);
    expden_kernel<<<(NN + 255) / 256, 256>>>(batch);
    pool_kernel<<<NN, 64>>>(batch);
    out_kernel<<<GG, 64>>>(out_W1, out_b1, out_W2, out_b2, out);
}

// round 4
// speedup vs baseline: 1.6618x; 1.6618x over previous
#include <cuda_runtime.h>
#include <cuda_bf16.h>
#include <cstdint>

#define NN 10000
#define EE 40000
#define GG 128
#define NF 92
#define EF 50
#define HH 64
#define NHD 10
#define GD 108
#define LL 5
#define FPH 640   // NH*H

#define HN_BLKS 79          // ceil(10000/128)
#define P_BLKS 313          // ceil(40000/128)

// ---------------- device scratch (static, no runtime alloc) ----------------
__device__ float g_h[NN * HH];
__device__ float g_init[NN * HH];
__device__ float g_ea[EE * HH];
__device__ float g_Hn[NN * FPH];     // h @ W[:64]   (25.6 MB)
__device__ float g_P[EE * FPH];      // ea @ W[64:]  (102.4 MB)
__device__ float g_agg[NN * HH];
__device__ float g_score[NN];
__device__ float g_smax[GG];
__device__ float g_den[GG];
__device__ float g_pool[GG * HH];

__device__ __forceinline__ float lrelu(float v) { return v > 0.f ? v : 0.2f * v; }

__device__ __forceinline__ float warp_sum(float v) {
    v += __shfl_down_sync(0xffffffffu, v, 16);
    v += __shfl_down_sync(0xffffffffu, v, 8);
    v += __shfl_down_sync(0xffffffffu, v, 4);
    v += __shfl_down_sync(0xffffffffu, v, 2);
    v += __shfl_down_sync(0xffffffffu, v, 1);
    return v;
}

__device__ __forceinline__ void atomicMaxFloat(float* addr, float val) {
    int* ai = (int*)addr;
    int old = *ai;
    while (__int_as_float(old) < val) {
        int assumed = old;
        old = atomicCAS(ai, assumed, __float_as_int(val));
        if (old == assumed) break;
    }
}

// ---- packed f32x2 helpers (sm_103a FFMA2 path) ----
__device__ __forceinline__ unsigned long long dup2(float a) {
    unsigned long long r;
    asm("mov.b64 %0, {%1, %1};" : "=l"(r) : "f"(a));
    return r;
}
__device__ __forceinline__ unsigned long long ffma2(unsigned long long a,
                                                    unsigned long long b,
                                                    unsigned long long c) {
    unsigned long long d;
    asm("fma.rn.f32x2 %0, %1, %2, %3;" : "=l"(d) : "l"(a), "l"(b), "l"(c));
    return d;
}
__device__ __forceinline__ float2 upk2(unsigned long long v) {
    float2 f;
    asm("mov.b64 {%0, %1}, %2;" : "=f"(f.x), "=f"(f.y) : "l"(v));
    return f;
}

// ---------------- embeddings ----------------
__global__ void embed_node_kernel(const float* __restrict__ x,
                                  const float* __restrict__ W,
                                  const float* __restrict__ b) {
    int n = blockIdx.x;
    int t = threadIdx.x;
    __shared__ float xs[NF];
    for (int k = t; k < NF; k += 64) xs[k] = x[n * NF + k];
    __syncthreads();
    float acc = b[t];
    #pragma unroll 4
    for (int k = 0; k < NF; k++) acc = fmaf(xs[k], W[k * HH + t], acc);
    float v = lrelu(acc);
    g_h[n * HH + t] = v;
    g_init[n * HH + t] = v;
}

__global__ void embed_edge_kernel(const float* __restrict__ ea,
                                  const float* __restrict__ W,
                                  const float* __restrict__ b) {
    int e = blockIdx.x;
    int t = threadIdx.x;
    __shared__ float xs[EF];
    if (t < EF) xs[t] = ea[e * EF + t];
    __syncthreads();
    float acc = b[t];
    #pragma unroll 5
    for (int k = 0; k < EF; k++) acc = fmaf(xs[k], W[k * HH + t], acc);
    g_ea[e * HH + t] = lrelu(acc);
}

__global__ void init_misc_kernel() {
    int idx = blockIdx.x * 256 + threadIdx.x;
    if (idx < NN * HH) g_agg[idx] = 0.f;
    if (idx < GG * HH) g_pool[idx] = 0.f;
    if (idx < GG) { g_smax[idx] = -3.0e38f; g_den[idx] = 0.f; }
}

// ---------------- layer GEMM (fused Hn + P) ---------------------------------
// C[M,640] = A[M,64] @ W[64,640], 128x128 tiles, 8x8 micro via f32x2.
// blocks [0,HN_BLKS): Hn ;  [HN_BLKS, HN_BLKS+P_BLKS): P.
struct GemmSM {
    float Ast[64][132];   // A transposed [k][m]
    float Bs[64][132];    // W chunk [k][n]
};

__global__ void __launch_bounds__(256, 2)
gemm_layer_kernel(const float* __restrict__ Wbase) {
    extern __shared__ char smraw[];
    GemmSM* s = (GemmSM*)smraw;

    const float* A;
    const float* W;
    float* C;
    int M, bm;
    if (blockIdx.x < HN_BLKS) {
        A = g_h;  W = Wbase;                   C = g_Hn; M = NN;
        bm = blockIdx.x * 128;
    } else {
        A = g_ea; W = Wbase + (size_t)HH * FPH; C = g_P;  M = EE;
        bm = (blockIdx.x - HN_BLKS) * 128;
    }
    int bn = blockIdx.y * 128;
    int tid = threadIdx.x;

    // load A tile [128 x 64] -> Ast[k][m] (transposed). flat float4 indexing.
    #pragma unroll
    for (int li = 0; li < 8; li++) {
        int i = tid + li * 256;          // float4 index, 2048 total
        int r = i >> 4;                  // row in tile 0..127
        int kc = (i & 15) * 4;           // k 0..63
        int m = bm + r;
        float4 v = make_float4(0.f, 0.f, 0.f, 0.f);
        if (m < M) v = *(const float4*)&A[(size_t)m * 64 + kc];
        s->Ast[kc + 0][r] = v.x;
        s->Ast[kc + 1][r] = v.y;
        s->Ast[kc + 2][r] = v.z;
        s->Ast[kc + 3][r] = v.w;
    }
    // load B tile [64 x 128]
    #pragma unroll
    for (int li = 0; li < 8; li++) {
        int i = tid + li * 256;          // float4 index, 2048 total
        int r = i >> 5;                  // k row 0..63
        int c = (i & 31) * 4;            // col 0..127
        float4 v = *(const float4*)&W[(size_t)r * FPH + bn + c];
        *(float4*)&s->Bs[r][c] = v;
    }
    __syncthreads();

    int tx = tid & 15;   // col groups: tx*4 and 64+tx*4
    int ty = tid >> 4;   // row groups: ty*4 and 64+ty*4

    unsigned long long acc[8][4] = {};   // [row(i<4: ty*4+i ; i>=4: 64+ty*4+i-4)][colpair]
    #pragma unroll 4
    for (int k = 0; k < 64; k++) {
        float4 a0 = *(const float4*)&s->Ast[k][ty * 4];
        float4 a1 = *(const float4*)&s->Ast[k][64 + ty * 4];
        ulonglong2 b0 = *(const ulonglong2*)&s->Bs[k][tx * 4];
        ulonglong2 b1 = *(const ulonglong2*)&s->Bs[k][64 + tx * 4];
        float av[8] = {a0.x, a0.y, a0.z, a0.w, a1.x, a1.y, a1.z, a1.w};
        #pragma unroll
        for (int i = 0; i < 8; i++) {
            unsigned long long ad = dup2(av[i]);
            acc[i][0] = ffma2(ad, b0.x, acc[i][0]);
            acc[i][1] = ffma2(ad, b0.y, acc[i][1]);
            acc[i][2] = ffma2(ad, b1.x, acc[i][2]);
            acc[i][3] = ffma2(ad, b1.y, acc[i][3]);
        }
    }

    #pragma unroll
    for (int i = 0; i < 8; i++) {
        int m = bm + (i < 4 ? ty * 4 + i : 64 + ty * 4 + (i - 4));
        if (m < M) {
            float2 p0 = upk2(acc[i][0]);
            float2 p1 = upk2(acc[i][1]);
            float2 p2 = upk2(acc[i][2]);
            float2 p3 = upk2(acc[i][3]);
            *(float4*)&C[(size_t)m * FPH + bn + tx * 4] =
                make_float4(p0.x, p0.y, p1.x, p1.y);
            *(float4*)&C[(size_t)m * FPH + bn + 64 + tx * 4] =
                make_float4(p2.x, p2.y, p3.x, p3.y);
        }
    }
}

// ---------------- fused edge kernel ----------------
// 4 edges per 256-thread block; 64 threads per edge
__global__ void edge_kernel(const float* __restrict__ att,
                            const float* __restrict__ gamma,
                            const float* __restrict__ beta,
                            const int* __restrict__ ei) {
    __shared__ float red[4][2][NHD];
    __shared__ float salpha[4][NHD];
    const float inv_std = 0.99999500003749969f; // 1/sqrt(1+1e-5)

    int tid = threadIdx.x;
    int grp = tid >> 6;
    int t = tid & 63;
    int e = blockIdx.x * 4 + grp;

    int row = ei[e];
    int col = ei[EE + e];

    const float* Pp = g_P + (size_t)e * FPH;
    const float* Hr = g_Hn + (size_t)row * FPH;
    const float* Hc = g_Hn + (size_t)col * FPH;

    float hj[NHD];
    float ap[NHD];
    #pragma unroll
    for (int nh = 0; nh < NHD; nh++) {
        int idx = nh * 64 + t;
        float p = Pp[idx];
        float vi = lrelu(Hr[idx] + p);
        float vj = lrelu(Hc[idx] + p);
        hj[nh] = vj;
        ap[nh] = fmaf(vi, att[nh * 128 + t], vj * att[nh * 128 + 64 + t]);
    }
    int warp_in_grp = t >> 5;
    #pragma unroll
    for (int nh = 0; nh < NHD; nh++) {
        float v = warp_sum(ap[nh]);
        if ((t & 31) == 0) red[grp][warp_in_grp][nh] = v;
    }
    __syncthreads();
    if (t == 0) {
        float a[NHD];
        float mx = -3.0e38f;
        #pragma unroll
        for (int nh = 0; nh < NHD; nh++) {
            float v = red[grp][0][nh] + red[grp][1][nh];
            v = lrelu(v);
            v = fmaf(v * inv_std, gamma[nh], beta[nh]);
            a[nh] = v;
            mx = fmaxf(mx, v);
        }
        float ssum = 0.f;
        #pragma unroll
        for (int nh = 0; nh < NHD; nh++) { a[nh] = __expf(a[nh] - mx); ssum += a[nh]; }
        float inv = 0.1f / ssum;  // fold mean-over-heads into alpha
        #pragma unroll
        for (int nh = 0; nh < NHD; nh++) salpha[grp][nh] = a[nh] * inv;
    }
    __syncthreads();
    float m = 0.f;
    #pragma unroll
    for (int nh = 0; nh < NHD; nh++) m = fmaf(salpha[grp][nh], hj[nh], m);
    atomicAdd(&g_agg[row * HH + t], m);
}

// ---------------- node update ----------------
__global__ void node_update_kernel(const float* __restrict__ b, int flags) {
    int idx = blockIdx.x * 256 + threadIdx.x;
    if (idx >= NN * HH) return;
    int t = idx & 63;
    float v = g_agg[idx] + b[t];
    if (flags & 1) v += g_h[idx];
    if (flags & 2) v += g_init[idx];
    g_h[idx] = v;
    g_agg[idx] = 0.f;
}

// ---------------- readout ----------------
__global__ void score_kernel(const int* __restrict__ batch,
                             const float* __restrict__ gfeat,
                             const float* __restrict__ W1,
                             const float* __restrict__ b1,
                             const float* __restrict__ W2,
                             const float* __restrict__ b2) {
    int n = blockIdx.x;
    int t = threadIdx.x;
    __shared__ float cat_s[HH + GD];
    __shared__ float wr[2];
    int bidx = batch[n];
    cat_s[t] = g_h[n * HH + t];
    for (int k = t; k < GD; k += 64) cat_s[HH + k] = gfeat[bidx * GD + k];
    __syncthreads();
    float acc = b1[t];
    #pragma unroll 4
    for (int k = 0; k < HH + GD; k++) acc = fmaf(cat_s[k], W1[k * HH + t], acc);
    float sv = lrelu(acc);
    float v = warp_sum(sv * W2[t]);
    if ((t & 31) == 0) wr[t >> 5] = v;
    __syncthreads();
    if (t == 0) g_score[n] = wr[0] + wr[1] + b2[0];
}

__global__ void smax_kernel(const int* __restrict__ batch) {
    int n = blockIdx.x * 256 + threadIdx.x;
    if (n >= NN) return;
    atomicMaxFloat(&g_smax[batch[n]], g_score[n]);
}

__global__ void expden_kernel(const int* __restrict__ batch) {
    int n = blockIdx.x * 256 + threadIdx.x;
    if (n >= NN) return;
    int b = batch[n];
    float ex = __expf(g_score[n] - g_smax[b]);
    g_score[n] = ex;
    atomicAdd(&g_den[b], ex);
}

__global__ void pool_kernel(const int* __restrict__ batch) {
    int n = blockIdx.x;
    int t = threadIdx.x;
    int b = batch[n];
    float w = g_score[n] / g_den[b];
    atomicAdd(&g_pool[b * HH + t], g_h[n * HH + t] * w);
}

__global__ void out_kernel(const float* __restrict__ W1,
                           const float* __restrict__ b1,
                           const float* __restrict__ W2,
                           const float* __restrict__ b2,
                           float* __restrict__ out) {
    int g = blockIdx.x;
    int t = threadIdx.x;
    __shared__ float ps[HH];
    __shared__ float wr[2];
    ps[t] = g_pool[g * HH + t];
    __syncthreads();
    float acc = b1[t];
    #pragma unroll 4
    for (int k = 0; k < HH; k++) acc = fmaf(ps[k], W1[k * HH + t], acc);
    float r = fmaxf(acc, 0.f);
    float v = warp_sum(r * W2[t]);
    if ((t & 31) == 0) wr[t >> 5] = v;
    __syncthreads();
    if (t == 0) out[g] = wr[0] + wr[1] + b2[0];
}

// ---------------- launch ----------------
extern "C" void kernel_launch(void* const* d_in, const int* in_sizes, int n_in,
                              void* d_out, int out_size) {
    const float* x        = (const float*)d_in[0];
    const int*   ei       = (const int*)  d_in[1];
    const float* eattr    = (const float*)d_in[2];
    const int*   batch    = (const int*)  d_in[3];
    const float* gfeat    = (const float*)d_in[4];
    const float* node_W   = (const float*)d_in[5];
    const float* node_b   = (const float*)d_in[6];
    const float* edge_W   = (const float*)d_in[7];
    const float* edge_b   = (const float*)d_in[8];
    const float* conv_W   = (const float*)d_in[9];
    const float* conv_att = (const float*)d_in[10];
    const float* conv_b   = (const float*)d_in[11];
    const float* conv_g   = (const float*)d_in[12];
    const float* conv_be  = (const float*)d_in[13];
    const float* ga_W1    = (const float*)d_in[14];
    const float* ga_b1    = (const float*)d_in[15];
    const float* ga_W2    = (const float*)d_in[16];
    const float* ga_b2    = (const float*)d_in[17];
    const float* out_W1   = (const float*)d_in[18];
    const float* out_b1   = (const float*)d_in[19];
    const float* out_W2   = (const float*)d_in[20];
    const float* out_b2   = (const float*)d_in[21];
    float* out = (float*)d_out;

    cudaFuncSetAttribute(gemm_layer_kernel,
                         cudaFuncAttributeMaxDynamicSharedMemorySize,
                         (int)sizeof(GemmSM));

    embed_node_kernel<<<NN, 64>>>(x, node_W, node_b);
    embed_edge_kernel<<<EE, 64>>>(eattr, edge_W, edge_b);
    init_misc_kernel<<<(NN * HH + 255) / 256, 256>>>();

    for (int i = 0; i < LL; i++) {
        const float* Wi = conv_W + (size_t)i * 2 * HH * FPH;
        gemm_layer_kernel<<<dim3(HN_BLKS + P_BLKS, FPH / 128), 256,
                            sizeof(GemmSM)>>>(Wi);
        edge_kernel<<<EE / 4, 256>>>(conv_att + (size_t)i * NHD * 2 * HH,
                                     conv_g + i * NHD, conv_be + i * NHD, ei);
        int flags = (i > 0 ? 1 : 0) | (i == LL - 1 ? 2 : 0);
        node_update_kernel<<<(NN * HH + 255) / 256, 256>>>(conv_b + i * HH, flags);
    }

    score_kernel<<<NN, 64>>>(batch, gfeat, ga_W1, ga_b1, ga_W2, ga_b2);
    smax_kernel<<<(NN + 255) / 256, 256>>>(batch);
    expden_kernel<<<(NN + 255) / 256, 256>>>(batch);
    pool_kernel<<<NN, 64>>>(batch);
    out_kernel<<<GG, 64>>>(out_W1, out_b1, out_W2, out_b2, out);
}

// round 5
// speedup vs baseline: 1.7573x; 1.0575x over previous
#include <cuda_runtime.h>
#include <cuda_bf16.h>
#include <cstdint>

#define NN 10000
#define EE 40000
#define GG 128
#define NF 92
#define EF 50
#define HH 64
#define NHD 10
#define GD 108
#define LL 5
#define FPH 640   // NH*H

#define HN_BLKS 79          // ceil(10000/128)
#define P_BLKS 313          // ceil(40000/128)

// ---------------- device scratch (static, no runtime alloc) ----------------
__device__ float g_h[NN * HH];
__device__ float g_init[NN * HH];
__device__ float g_ea[EE * HH];
__device__ float g_Hn[NN * FPH];     // h @ W[:64]   (25.6 MB)
__device__ float g_P[EE * FPH];      // ea @ W[64:]  (102.4 MB)
__device__ float g_agg[NN * HH];
__device__ float g_score[NN];
__device__ float g_smax[GG];
__device__ float g_den[GG];
__device__ float g_pool[GG * HH];

__device__ __forceinline__ float lrelu(float v) { return v > 0.f ? v : 0.2f * v; }

__device__ __forceinline__ float warp_sum(float v) {
    v += __shfl_down_sync(0xffffffffu, v, 16);
    v += __shfl_down_sync(0xffffffffu, v, 8);
    v += __shfl_down_sync(0xffffffffu, v, 4);
    v += __shfl_down_sync(0xffffffffu, v, 2);
    v += __shfl_down_sync(0xffffffffu, v, 1);
    return v;
}

__device__ __forceinline__ void atomicMaxFloat(float* addr, float val) {
    int* ai = (int*)addr;
    int old = *ai;
    while (__int_as_float(old) < val) {
        int assumed = old;
        old = atomicCAS(ai, assumed, __float_as_int(val));
        if (old == assumed) break;
    }
}

// ---- packed f32x2 helpers (sm_103a FFMA2 path) ----
__device__ __forceinline__ unsigned long long dup2(float a) {
    unsigned long long r;
    asm("mov.b64 %0, {%1, %1};" : "=l"(r) : "f"(a));
    return r;
}
__device__ __forceinline__ unsigned long long ffma2(unsigned long long a,
                                                    unsigned long long b,
                                                    unsigned long long c) {
    unsigned long long d;
    asm("fma.rn.f32x2 %0, %1, %2, %3;" : "=l"(d) : "l"(a), "l"(b), "l"(c));
    return d;
}
__device__ __forceinline__ float2 upk2(unsigned long long v) {
    float2 f;
    asm("mov.b64 {%0, %1}, %2;" : "=f"(f.x), "=f"(f.y) : "l"(v));
    return f;
}

// ---------------- embeddings ----------------
__global__ void embed_node_kernel(const float* __restrict__ x,
                                  const float* __restrict__ W,
                                  const float* __restrict__ b) {
    int n = blockIdx.x;
    int t = threadIdx.x;
    __shared__ float xs[NF];
    for (int k = t; k < NF; k += 64) xs[k] = x[n * NF + k];
    __syncthreads();
    float acc = b[t];
    #pragma unroll 4
    for (int k = 0; k < NF; k++) acc = fmaf(xs[k], W[k * HH + t], acc);
    float v = lrelu(acc);
    g_h[n * HH + t] = v;
    g_init[n * HH + t] = v;
}

__global__ void embed_edge_kernel(const float* __restrict__ ea,
                                  const float* __restrict__ W,
                                  const float* __restrict__ b) {
    int e = blockIdx.x;
    int t = threadIdx.x;
    __shared__ float xs[EF];
    if (t < EF) xs[t] = ea[e * EF + t];
    __syncthreads();
    float acc = b[t];
    #pragma unroll 5
    for (int k = 0; k < EF; k++) acc = fmaf(xs[k], W[k * HH + t], acc);
    g_ea[e * HH + t] = lrelu(acc);
}

__global__ void init_misc_kernel() {
    int idx = blockIdx.x * 256 + threadIdx.x;
    if (idx < NN * HH) g_agg[idx] = 0.f;
    if (idx < GG * HH) g_pool[idx] = 0.f;
    if (idx < GG) { g_smax[idx] = -3.0e38f; g_den[idx] = 0.f; }
}

// ---------------- layer GEMM (fused Hn + P) ---------------------------------
// C[M,640] = A[M,64] @ W[64,640], 128x128 tiles, 8x8 micro via f32x2.
struct GemmSM {
    float Ast[64][132];   // A transposed [k][m]
    float Bs[64][132];    // W chunk [k][n]
};

__global__ void __launch_bounds__(256, 2)
gemm_layer_kernel(const float* __restrict__ Wbase) {
    extern __shared__ char smraw[];
    GemmSM* s = (GemmSM*)smraw;

    const float* A;
    const float* W;
    float* C;
    int M, bm;
    if (blockIdx.x < HN_BLKS) {
        A = g_h;  W = Wbase;                   C = g_Hn; M = NN;
        bm = blockIdx.x * 128;
    } else {
        A = g_ea; W = Wbase + (size_t)HH * FPH; C = g_P;  M = EE;
        bm = (blockIdx.x - HN_BLKS) * 128;
    }
    int bn = blockIdx.y * 128;
    int tid = threadIdx.x;

    #pragma unroll
    for (int li = 0; li < 8; li++) {
        int i = tid + li * 256;
        int r = i >> 4;
        int kc = (i & 15) * 4;
        int m = bm + r;
        float4 v = make_float4(0.f, 0.f, 0.f, 0.f);
        if (m < M) v = *(const float4*)&A[(size_t)m * 64 + kc];
        s->Ast[kc + 0][r] = v.x;
        s->Ast[kc + 1][r] = v.y;
        s->Ast[kc + 2][r] = v.z;
        s->Ast[kc + 3][r] = v.w;
    }
    #pragma unroll
    for (int li = 0; li < 8; li++) {
        int i = tid + li * 256;
        int r = i >> 5;
        int c = (i & 31) * 4;
        float4 v = *(const float4*)&W[(size_t)r * FPH + bn + c];
        *(float4*)&s->Bs[r][c] = v;
    }
    __syncthreads();

    int tx = tid & 15;
    int ty = tid >> 4;

    unsigned long long acc[8][4] = {};
    #pragma unroll 4
    for (int k = 0; k < 64; k++) {
        float4 a0 = *(const float4*)&s->Ast[k][ty * 4];
        float4 a1 = *(const float4*)&s->Ast[k][64 + ty * 4];
        ulonglong2 b0 = *(const ulonglong2*)&s->Bs[k][tx * 4];
        ulonglong2 b1 = *(const ulonglong2*)&s->Bs[k][64 + tx * 4];
        float av[8] = {a0.x, a0.y, a0.z, a0.w, a1.x, a1.y, a1.z, a1.w};
        #pragma unroll
        for (int i = 0; i < 8; i++) {
            unsigned long long ad = dup2(av[i]);
            acc[i][0] = ffma2(ad, b0.x, acc[i][0]);
            acc[i][1] = ffma2(ad, b0.y, acc[i][1]);
            acc[i][2] = ffma2(ad, b1.x, acc[i][2]);
            acc[i][3] = ffma2(ad, b1.y, acc[i][3]);
        }
    }

    #pragma unroll
    for (int i = 0; i < 8; i++) {
        int m = bm + (i < 4 ? ty * 4 + i : 64 + ty * 4 + (i - 4));
        if (m < M) {
            float2 p0 = upk2(acc[i][0]);
            float2 p1 = upk2(acc[i][1]);
            float2 p2 = upk2(acc[i][2]);
            float2 p3 = upk2(acc[i][3]);
            *(float4*)&C[(size_t)m * FPH + bn + tx * 4] =
                make_float4(p0.x, p0.y, p1.x, p1.y);
            *(float4*)&C[(size_t)m * FPH + bn + 64 + tx * 4] =
                make_float4(p2.x, p2.y, p3.x, p3.y);
        }
    }
}

// ---------------- edge kernel: warp-per-edge, float4 loads -------------------
// Lane layout: half = lane>>4 (even/odd head), c4 = (lane&15)*4 col-in-head.
// Phase p handles cols [128p, 128p+128) = heads 2p (lanes 0-15) and 2p+1 (16-31).
__global__ void __launch_bounds__(256)
edge_kernel(const float* __restrict__ att,
            const float* __restrict__ gamma,
            const float* __restrict__ beta,
            const int* __restrict__ ei) {
    const float inv_std = 0.99999500003749969f; // 1/sqrt(1+1e-5)
    int lane = threadIdx.x & 31;
    int warp = threadIdx.x >> 5;
    int e = blockIdx.x * 8 + warp;

    int row = ei[e];
    int col = ei[EE + e];
    int half = lane >> 4;
    int c4 = (lane & 15) * 4;

    const float* Pp = g_P + (size_t)e * FPH;
    const float* Hr = g_Hn + (size_t)row * FPH;
    const float* Hc = g_Hn + (size_t)col * FPH;

    float hj[5][4];
    float ap[5];
    #pragma unroll
    for (int p = 0; p < 5; p++) {
        int off = p * 128 + lane * 4;
        float4 pv = *(const float4*)(Pp + off);
        float4 hr = *(const float4*)(Hr + off);
        float4 hc = *(const float4*)(Hc + off);
        int hd = 2 * p + half;
        float4 a1 = *(const float4*)(att + hd * 128 + c4);
        float4 a2 = *(const float4*)(att + hd * 128 + 64 + c4);
        float pr[4]  = {pv.x, pv.y, pv.z, pv.w};
        float hrr[4] = {hr.x, hr.y, hr.z, hr.w};
        float hcr[4] = {hc.x, hc.y, hc.z, hc.w};
        float a1r[4] = {a1.x, a1.y, a1.z, a1.w};
        float a2r[4] = {a2.x, a2.y, a2.z, a2.w};
        float sacc = 0.f;
        #pragma unroll
        for (int q = 0; q < 4; q++) {
            float hi  = lrelu(hrr[q] + pr[q]);
            float hjq = lrelu(hcr[q] + pr[q]);
            hj[p][q] = hjq;
            sacc = fmaf(hi, a1r[q], sacc);
            sacc = fmaf(hjq, a2r[q], sacc);
        }
        ap[p] = sacc;
    }
    // reduce attention dot within each 16-lane half (all lanes get the sum)
    #pragma unroll
    for (int p = 0; p < 5; p++) {
        #pragma unroll
        for (int off = 8; off > 0; off >>= 1)
            ap[p] += __shfl_xor_sync(0xffffffffu, ap[p], off, 16);
    }
    // affine + softmax over 10 heads (5 per half, cross-half via shfl_xor 16)
    float v[5];
    float mx = -3.0e38f;
    #pragma unroll
    for (int p = 0; p < 5; p++) {
        int hd = 2 * p + half;
        float t = lrelu(ap[p]);
        t = fmaf(t * inv_std, gamma[hd], beta[hd]);
        v[p] = t;
        mx = fmaxf(mx, t);
    }
    mx = fmaxf(mx, __shfl_xor_sync(0xffffffffu, mx, 16));
    float ssum = 0.f;
    #pragma unroll
    for (int p = 0; p < 5; p++) { v[p] = __expf(v[p] - mx); ssum += v[p]; }
    ssum += __shfl_xor_sync(0xffffffffu, ssum, 16);
    float sc = 0.1f / ssum;   // fold mean-over-heads
    // msg for my 4 cols over my 5 heads, then combine with partner half
    float m[4] = {0.f, 0.f, 0.f, 0.f};
    #pragma unroll
    for (int p = 0; p < 5; p++) {
        float al = v[p] * sc;
        #pragma unroll
        for (int q = 0; q < 4; q++) m[q] = fmaf(al, hj[p][q], m[q]);
    }
    #pragma unroll
    for (int q = 0; q < 4; q++) m[q] += __shfl_xor_sync(0xffffffffu, m[q], 16);
    float* dst = g_agg + row * HH + c4;
    if (half == 0) { atomicAdd(dst + 0, m[0]); atomicAdd(dst + 1, m[1]); }
    else           { atomicAdd(dst + 2, m[2]); atomicAdd(dst + 3, m[3]); }
}

// ---------------- node update ----------------
__global__ void node_update_kernel(const float* __restrict__ b, int flags) {
    int idx = blockIdx.x * 256 + threadIdx.x;
    if (idx >= NN * HH) return;
    int t = idx & 63;
    float v = g_agg[idx] + b[t];
    if (flags & 1) v += g_h[idx];
    if (flags & 2) v += g_init[idx];
    g_h[idx] = v;
    g_agg[idx] = 0.f;
}

// ---------------- readout ----------------
__global__ void score_kernel(const int* __restrict__ batch,
                             const float* __restrict__ gfeat,
                             const float* __restrict__ W1,
                             const float* __restrict__ b1,
                             const float* __restrict__ W2,
                             const float* __restrict__ b2) {
    int n = blockIdx.x;
    int t = threadIdx.x;
    __shared__ float cat_s[HH + GD];
    __shared__ float wr[2];
    int bidx = batch[n];
    cat_s[t] = g_h[n * HH + t];
    for (int k = t; k < GD; k += 64) cat_s[HH + k] = gfeat[bidx * GD + k];
    __syncthreads();
    float acc = b1[t];
    #pragma unroll 4
    for (int k = 0; k < HH + GD; k++) acc = fmaf(cat_s[k], W1[k * HH + t], acc);
    float sv = lrelu(acc);
    float v = warp_sum(sv * W2[t]);
    if ((t & 31) == 0) wr[t >> 5] = v;
    __syncthreads();
    if (t == 0) g_score[n] = wr[0] + wr[1] + b2[0];
}

__global__ void smax_kernel(const int* __restrict__ batch) {
    int n = blockIdx.x * 256 + threadIdx.x;
    if (n >= NN) return;
    atomicMaxFloat(&g_smax[batch[n]], g_score[n]);
}

__global__ void expden_kernel(const int* __restrict__ batch) {
    int n = blockIdx.x * 256 + threadIdx.x;
    if (n >= NN) return;
    int b = batch[n];
    float ex = __expf(g_score[n] - g_smax[b]);
    g_score[n] = ex;
    atomicAdd(&g_den[b], ex);
}

__global__ void pool_kernel(const int* __restrict__ batch) {
    int n = blockIdx.x;
    int t = threadIdx.x;
    int b = batch[n];
    float w = g_score[n] / g_den[b];
    atomicAdd(&g_pool[b * HH + t], g_h[n * HH + t] * w);
}

__global__ void out_kernel(const float* __restrict__ W1,
                           const float* __restrict__ b1,
                           const float* __restrict__ W2,
                           const float* __restrict__ b2,
                           float* __restrict__ out) {
    int g = blockIdx.x;
    int t = threadIdx.x;
    __shared__ float ps[HH];
    __shared__ float wr[2];
    ps[t] = g_pool[g * HH + t];
    __syncthreads();
    float acc = b1[t];
    #pragma unroll 4
    for (int k = 0; k < HH; k++) acc = fmaf(ps[k], W1[k * HH + t], acc);
    float r = fmaxf(acc, 0.f);
    float v = warp_sum(r * W2[t]);
    if ((t & 31) == 0) wr[t >> 5] = v;
    __syncthreads();
    if (t == 0) out[g] = wr[0] + wr[1] + b2[0];
}

// ---------------- launch ----------------
extern "C" void kernel_launch(void* const* d_in, const int* in_sizes, int n_in,
                              void* d_out, int out_size) {
    const float* x        = (const float*)d_in[0];
    const int*   ei       = (const int*)  d_in[1];
    const float* eattr    = (const float*)d_in[2];
    const int*   batch    = (const int*)  d_in[3];
    const float* gfeat    = (const float*)d_in[4];
    const float* node_W   = (const float*)d_in[5];
    const float* node_b   = (const float*)d_in[6];
    const float* edge_W   = (const float*)d_in[7];
    const float* edge_b   = (const float*)d_in[8];
    const float* conv_W   = (const float*)d_in[9];
    const float* conv_att = (const float*)d_in[10];
    const float* conv_b   = (const float*)d_in[11];
    const float* conv_g   = (const float*)d_in[12];
    const float* conv_be  = (const float*)d_in[13];
    const float* ga_W1    = (const float*)d_in[14];
    const float* ga_b1    = (const float*)d_in[15];
    const float* ga_W2    = (const float*)d_in[16];
    const float* ga_b2    = (const float*)d_in[17];
    const float* out_W1   = (const float*)d_in[18];
    const float* out_b1   = (const float*)d_in[19];
    const float* out_W2   = (const float*)d_in[20];
    const float* out_b2   = (const float*)d_in[21];
    float* out = (float*)d_out;

    cudaFuncSetAttribute(gemm_layer_kernel,
                         cudaFuncAttributeMaxDynamicSharedMemorySize,
                         (int)sizeof(GemmSM));

    embed_node_kernel<<<NN, 64>>>(x, node_W, node_b);
    embed_edge_kernel<<<EE, 64>>>(eattr, edge_W, edge_b);
    init_misc_kernel<<<(NN * HH + 255) / 256, 256>>>();

    for (int i = 0; i < LL; i++) {
        const float* Wi = conv_W + (size_t)i * 2 * HH * FPH;
        gemm_layer_kernel<<<dim3(HN_BLKS + P_BLKS, FPH / 128), 256,
                            sizeof(GemmSM)>>>(Wi);
        edge_kernel<<<EE / 8, 256>>>(conv_att + (size_t)i * NHD * 2 * HH,
                                     conv_g + i * NHD, conv_be + i * NHD, ei);
        int flags = (i > 0 ? 1 : 0) | (i == LL - 1 ? 2 : 0);
        node_update_kernel<<<(NN * HH + 255) / 256, 256>>>(conv_b + i * HH, flags);
    }

    score_kernel<<<NN, 64>>>(batch, gfeat, ga_W1, ga_b1, ga_W2, ga_b2);
    smax_kernel<<<(NN + 255) / 256, 256>>>(batch);
    expden_kernel<<<(NN + 255) / 256, 256>>>(batch);
    pool_kernel<<<NN, 64>>>(batch);
    out_kernel<<<GG, 64>>>(out_W1, out_b1, out_W2, out_b2, out);
}

// round 6
// speedup vs baseline: 2.1696x; 1.2346x over previous
#include <cuda_runtime.h>
#include <cuda_bf16.h>
#include <cstdint>

#define NN 10000
#define EE 40000
#define GG 128
#define NF 92
#define EF 50
#define HH 64
#define NHD 10
#define GD 108
#define LL 5
#define FPH 640   // NH*H

#define HN_BLKS 79          // ceil(10000/128)
#define P_BLKS 313          // ceil(40000/128)

// ---------------- device scratch (static, no runtime alloc) ----------------
__device__ float g_h[NN * HH];
__device__ float g_init[NN * HH];
__device__ float g_ea[EE * HH];
__device__ float g_Hn[NN * FPH];     // h @ W[:64]   (25.6 MB)
__device__ float g_P[EE * FPH];      // ea @ W[64:]  (102.4 MB)
__device__ float g_agg[NN * HH];
__device__ float g_score[NN];
__device__ float g_smax[GG];
__device__ float g_den[GG];
__device__ float g_pool[GG * HH];

__device__ __forceinline__ float lrelu(float v) { return v > 0.f ? v : 0.2f * v; }

__device__ __forceinline__ float warp_sum(float v) {
    v += __shfl_down_sync(0xffffffffu, v, 16);
    v += __shfl_down_sync(0xffffffffu, v, 8);
    v += __shfl_down_sync(0xffffffffu, v, 4);
    v += __shfl_down_sync(0xffffffffu, v, 2);
    v += __shfl_down_sync(0xffffffffu, v, 1);
    return v;
}

__device__ __forceinline__ void atomicMaxFloat(float* addr, float val) {
    int* ai = (int*)addr;
    int old = *ai;
    while (__int_as_float(old) < val) {
        int assumed = old;
        old = atomicCAS(ai, assumed, __float_as_int(val));
        if (old == assumed) break;
    }
}

__device__ __forceinline__ uint32_t tf32_of(float f) {
    uint32_t r;
    asm("cvt.rna.tf32.f32 %0, %1;" : "=r"(r) : "f"(f));
    return r;
}

// k-position permute: logical k (0..63) -> storage pos so (k, k+4) are adjacent
__device__ __forceinline__ int kpos(int k) {
    return (k >> 3) * 8 + 2 * (k & 3) + ((k >> 2) & 1);
}

// ---------------- embeddings ----------------
__global__ void embed_node_kernel(const float* __restrict__ x,
                                  const float* __restrict__ W,
                                  const float* __restrict__ b) {
    int n = blockIdx.x;
    int t = threadIdx.x;
    __shared__ float xs[NF];
    for (int k = t; k < NF; k += 64) xs[k] = x[n * NF + k];
    __syncthreads();
    float acc = b[t];
    #pragma unroll 4
    for (int k = 0; k < NF; k++) acc = fmaf(xs[k], W[k * HH + t], acc);
    float v = lrelu(acc);
    g_h[n * HH + t] = v;
    g_init[n * HH + t] = v;
}

__global__ void embed_edge_kernel(const float* __restrict__ ea,
                                  const float* __restrict__ W,
                                  const float* __restrict__ b) {
    int e = blockIdx.x;
    int t = threadIdx.x;
    __shared__ float xs[EF];
    if (t < EF) xs[t] = ea[e * EF + t];
    __syncthreads();
    float acc = b[t];
    #pragma unroll 5
    for (int k = 0; k < EF; k++) acc = fmaf(xs[k], W[k * HH + t], acc);
    g_ea[e * HH + t] = lrelu(acc);
}

__global__ void init_misc_kernel() {
    int idx = blockIdx.x * 256 + threadIdx.x;
    if (idx < NN * HH) g_agg[idx] = 0.f;
    if (idx < GG * HH) g_pool[idx] = 0.f;
    if (idx < GG) { g_smax[idx] = -3.0e38f; g_den[idx] = 0.f; }
}

// ---------------- layer GEMM (tf32 tensor cores) -----------------------------
// C[M,640] = A[M,64] @ W[64,640], 128x128 tile, 8 warps (2m x 4n), warp 64x32.
// mma.sync.aligned.m16n8k8.row.col.f32.tf32.tf32.f32
struct GemmSM {
    float As[128 * 72];   // [m][kpos], pitch 72
    float Bs[128 * 72];   // [n][kpos ^ swz], pitch 72
};

__global__ void __launch_bounds__(256, 2)
gemm_layer_kernel(const float* __restrict__ Wbase) {
    extern __shared__ char smraw[];
    GemmSM* s = (GemmSM*)smraw;

    const float* A;
    const float* W;
    float* C;
    int M, bm;
    if (blockIdx.x < HN_BLKS) {
        A = g_h;  W = Wbase;                    C = g_Hn; M = NN;
        bm = blockIdx.x * 128;
    } else {
        A = g_ea; W = Wbase + (size_t)HH * FPH; C = g_P;  M = EE;
        bm = (blockIdx.x - HN_BLKS) * 128;
    }
    int bn = blockIdx.y * 128;
    int tid = threadIdx.x;

    // ---- load A tile [128 x 64] -> As[m][kpos] (tf32) ----
    #pragma unroll
    for (int li = 0; li < 8; li++) {
        int i = tid + li * 256;          // float4 unit
        int r = i >> 4;                  // 0..127
        int kc = (i & 15) * 4;           // 0..60
        int m = bm + r;
        float4 v = make_float4(0.f, 0.f, 0.f, 0.f);
        if (m < M) v = *(const float4*)&A[(size_t)m * 64 + kc];
        float vv[4] = {v.x, v.y, v.z, v.w};
        #pragma unroll
        for (int q = 0; q < 4; q++)
            s->As[r * 72 + kpos(kc + q)] = __uint_as_float(tf32_of(vv[q]));
    }
    // ---- load B tile W[64][128] -> Bs[n][kpos^swz] (tf32) ----
    #pragma unroll
    for (int li = 0; li < 8; li++) {
        int i = tid + li * 256;
        int r = i >> 5;                  // k row 0..63
        int c = (i & 31) * 4;            // n 0..124
        float4 v = *(const float4*)&W[(size_t)r * FPH + bn + c];
        float vv[4] = {v.x, v.y, v.z, v.w};
        int kp = kpos(r);
        #pragma unroll
        for (int q = 0; q < 4; q++) {
            int n = c + q;
            int colp = kp ^ (((n >> 2) & 7) << 3);
            s->Bs[n * 72 + colp] = __uint_as_float(tf32_of(vv[q]));
        }
    }
    __syncthreads();

    int lane = tid & 31;
    int warp = tid >> 5;
    int warp_m = warp >> 2;     // 0..1 -> m offset *64
    int warp_n = warp & 3;      // 0..3 -> n offset *32
    int g = lane >> 2;          // 0..7
    int t = lane & 3;           // 0..3

    float acc[4][4][4];
    #pragma unroll
    for (int mt = 0; mt < 4; mt++)
        #pragma unroll
        for (int nt = 0; nt < 4; nt++)
            #pragma unroll
            for (int q = 0; q < 4; q++) acc[mt][nt][q] = 0.f;

    #pragma unroll
    for (int ks = 0; ks < 8; ks++) {
        uint32_t a[4][4];
        #pragma unroll
        for (int mt = 0; mt < 4; mt++) {
            int row = warp_m * 64 + mt * 16 + g;
            float2 p02 = *(const float2*)&s->As[row * 72 + ks * 8 + 2 * t];
            float2 p13 = *(const float2*)&s->As[(row + 8) * 72 + ks * 8 + 2 * t];
            a[mt][0] = __float_as_uint(p02.x);
            a[mt][2] = __float_as_uint(p02.y);
            a[mt][1] = __float_as_uint(p13.x);
            a[mt][3] = __float_as_uint(p13.y);
        }
        uint32_t b[4][2];
        #pragma unroll
        for (int nt = 0; nt < 4; nt++) {
            int n = warp_n * 32 + nt * 8 + g;
            int colp = (ks * 8 + 2 * t) ^ (((n >> 2) & 7) << 3);
            float2 q01 = *(const float2*)&s->Bs[n * 72 + colp];
            b[nt][0] = __float_as_uint(q01.x);
            b[nt][1] = __float_as_uint(q01.y);
        }
        #pragma unroll
        for (int mt = 0; mt < 4; mt++)
            #pragma unroll
            for (int nt = 0; nt < 4; nt++) {
                asm volatile(
                    "mma.sync.aligned.m16n8k8.row.col.f32.tf32.tf32.f32 "
                    "{%0,%1,%2,%3}, {%4,%5,%6,%7}, {%8,%9}, {%0,%1,%2,%3};"
                    : "+f"(acc[mt][nt][0]), "+f"(acc[mt][nt][1]),
                      "+f"(acc[mt][nt][2]), "+f"(acc[mt][nt][3])
                    : "r"(a[mt][0]), "r"(a[mt][1]), "r"(a[mt][2]), "r"(a[mt][3]),
                      "r"(b[nt][0]), "r"(b[nt][1]));
            }
    }

    // ---- epilogue ----
    #pragma unroll
    for (int mt = 0; mt < 4; mt++) {
        int row0 = bm + warp_m * 64 + mt * 16 + g;
        int row1 = row0 + 8;
        #pragma unroll
        for (int nt = 0; nt < 4; nt++) {
            int col = bn + warp_n * 32 + nt * 8 + 2 * t;
            if (row0 < M)
                *(float2*)&C[(size_t)row0 * FPH + col] =
                    make_float2(acc[mt][nt][0], acc[mt][nt][1]);
            if (row1 < M)
                *(float2*)&C[(size_t)row1 * FPH + col] =
                    make_float2(acc[mt][nt][2], acc[mt][nt][3]);
        }
    }
}

// ---------------- edge kernel: warp-per-edge, float4 loads -------------------
__global__ void __launch_bounds__(256)
edge_kernel(const float* __restrict__ att,
            const float* __restrict__ gamma,
            const float* __restrict__ beta,
            const int* __restrict__ ei) {
    const float inv_std = 0.99999500003749969f; // 1/sqrt(1+1e-5)
    int lane = threadIdx.x & 31;
    int warp = threadIdx.x >> 5;
    int e = blockIdx.x * 8 + warp;

    int row = ei[e];
    int col = ei[EE + e];
    int half = lane >> 4;
    int c4 = (lane & 15) * 4;

    const float* Pp = g_P + (size_t)e * FPH;
    const float* Hr = g_Hn + (size_t)row * FPH;
    const float* Hc = g_Hn + (size_t)col * FPH;

    float hj[5][4];
    float ap[5];
    #pragma unroll
    for (int p = 0; p < 5; p++) {
        int off = p * 128 + lane * 4;
        float4 pv = *(const float4*)(Pp + off);
        float4 hr = *(const float4*)(Hr + off);
        float4 hc = *(const float4*)(Hc + off);
        int hd = 2 * p + half;
        float4 a1 = *(const float4*)(att + hd * 128 + c4);
        float4 a2 = *(const float4*)(att + hd * 128 + 64 + c4);
        float pr[4]  = {pv.x, pv.y, pv.z, pv.w};
        float hrr[4] = {hr.x, hr.y, hr.z, hr.w};
        float hcr[4] = {hc.x, hc.y, hc.z, hc.w};
        float a1r[4] = {a1.x, a1.y, a1.z, a1.w};
        float a2r[4] = {a2.x, a2.y, a2.z, a2.w};
        float sacc = 0.f;
        #pragma unroll
        for (int q = 0; q < 4; q++) {
            float hi  = lrelu(hrr[q] + pr[q]);
            float hjq = lrelu(hcr[q] + pr[q]);
            hj[p][q] = hjq;
            sacc = fmaf(hi, a1r[q], sacc);
            sacc = fmaf(hjq, a2r[q], sacc);
        }
        ap[p] = sacc;
    }
    #pragma unroll
    for (int p = 0; p < 5; p++) {
        #pragma unroll
        for (int off = 8; off > 0; off >>= 1)
            ap[p] += __shfl_xor_sync(0xffffffffu, ap[p], off, 16);
    }
    float v[5];
    float mx = -3.0e38f;
    #pragma unroll
    for (int p = 0; p < 5; p++) {
        int hd = 2 * p + half;
        float t = lrelu(ap[p]);
        t = fmaf(t * inv_std, gamma[hd], beta[hd]);
        v[p] = t;
        mx = fmaxf(mx, t);
    }
    mx = fmaxf(mx, __shfl_xor_sync(0xffffffffu, mx, 16));
    float ssum = 0.f;
    #pragma unroll
    for (int p = 0; p < 5; p++) { v[p] = __expf(v[p] - mx); ssum += v[p]; }
    ssum += __shfl_xor_sync(0xffffffffu, ssum, 16);
    float sc = 0.1f / ssum;
    float m[4] = {0.f, 0.f, 0.f, 0.f};
    #pragma unroll
    for (int p = 0; p < 5; p++) {
        float al = v[p] * sc;
        #pragma unroll
        for (int q = 0; q < 4; q++) m[q] = fmaf(al, hj[p][q], m[q]);
    }
    #pragma unroll
    for (int q = 0; q < 4; q++) m[q] += __shfl_xor_sync(0xffffffffu, m[q], 16);
    float* dst = g_agg + row * HH + c4;
    if (half == 0) { atomicAdd(dst + 0, m[0]); atomicAdd(dst + 1, m[1]); }
    else           { atomicAdd(dst + 2, m[2]); atomicAdd(dst + 3, m[3]); }
}

// ---------------- node update ----------------
__global__ void node_update_kernel(const float* __restrict__ b, int flags) {
    int idx = blockIdx.x * 256 + threadIdx.x;
    if (idx >= NN * HH) return;
    int t = idx & 63;
    float v = g_agg[idx] + b[t];
    if (flags & 1) v += g_h[idx];
    if (flags & 2) v += g_init[idx];
    g_h[idx] = v;
    g_agg[idx] = 0.f;
}

// ---------------- readout ----------------
__global__ void score_kernel(const int* __restrict__ batch,
                             const float* __restrict__ gfeat,
                             const float* __restrict__ W1,
                             const float* __restrict__ b1,
                             const float* __restrict__ W2,
                             const float* __restrict__ b2) {
    int n = blockIdx.x;
    int t = threadIdx.x;
    __shared__ float cat_s[HH + GD];
    __shared__ float wr[2];
    int bidx = batch[n];
    cat_s[t] = g_h[n * HH + t];
    for (int k = t; k < GD; k += 64) cat_s[HH + k] = gfeat[bidx * GD + k];
    __syncthreads();
    float acc = b1[t];
    #pragma unroll 4
    for (int k = 0; k < HH + GD; k++) acc = fmaf(cat_s[k], W1[k * HH + t], acc);
    float sv = lrelu(acc);
    float v = warp_sum(sv * W2[t]);
    if ((t & 31) == 0) wr[t >> 5] = v;
    __syncthreads();
    if (t == 0) g_score[n] = wr[0] + wr[1] + b2[0];
}

__global__ void smax_kernel(const int* __restrict__ batch) {
    int n = blockIdx.x * 256 + threadIdx.x;
    if (n >= NN) return;
    atomicMaxFloat(&g_smax[batch[n]], g_score[n]);
}

__global__ void expden_kernel(const int* __restrict__ batch) {
    int n = blockIdx.x * 256 + threadIdx.x;
    if (n >= NN) return;
    int b = batch[n];
    float ex = __expf(g_score[n] - g_smax[b]);
    g_score[n] = ex;
    atomicAdd(&g_den[b], ex);
}

__global__ void pool_kernel(const int* __restrict__ batch) {
    int n = blockIdx.x;
    int t = threadIdx.x;
    int b = batch[n];
    float w = g_score[n] / g_den[b];
    atomicAdd(&g_pool[b * HH + t], g_h[n * HH + t] * w);
}

__global__ void out_kernel(const float* __restrict__ W1,
                           const float* __restrict__ b1,
                           const float* __restrict__ W2,
                           const float* __restrict__ b2,
                           float* __restrict__ out) {
    int g = blockIdx.x;
    int t = threadIdx.x;
    __shared__ float ps[HH];
    __shared__ float wr[2];
    ps[t] = g_pool[g * HH + t];
    __syncthreads();
    float acc = b1[t];
    #pragma unroll 4
    for (int k = 0; k < HH; k++) acc = fmaf(ps[k], W1[k * HH + t], acc);
    float r = fmaxf(acc, 0.f);
    float v = warp_sum(r * W2[t]);
    if ((t & 31) == 0) wr[t >> 5] = v;
    __syncthreads();
    if (t == 0) out[g] = wr[0] + wr[1] + b2[0];
}

// ---------------- launch ----------------
extern "C" void kernel_launch(void* const* d_in, const int* in_sizes, int n_in,
                              void* d_out, int out_size) {
    const float* x        = (const float*)d_in[0];
    const int*   ei       = (const int*)  d_in[1];
    const float* eattr    = (const float*)d_in[2];
    const int*   batch    = (const int*)  d_in[3];
    const float* gfeat    = (const float*)d_in[4];
    const float* node_W   = (const float*)d_in[5];
    const float* node_b   = (const float*)d_in[6];
    const float* edge_W   = (const float*)d_in[7];
    const float* edge_b   = (const float*)d_in[8];
    const float* conv_W   = (const float*)d_in[9];
    const float* conv_att = (const float*)d_in[10];
    const float* conv_b   = (const float*)d_in[11];
    const float* conv_g   = (const float*)d_in[12];
    const float* conv_be  = (const float*)d_in[13];
    const float* ga_W1    = (const float*)d_in[14];
    const float* ga_b1    = (const float*)d_in[15];
    const float* ga_W2    = (const float*)d_in[16];
    const float* ga_b2    = (const float*)d_in[17];
    const float* out_W1   = (const float*)d_in[18];
    const float* out_b1   = (const float*)d_in[19];
    const float* out_W2   = (const float*)d_in[20];
    const float* out_b2   = (const float*)d_in[21];
    float* out = (float*)d_out;

    cudaFuncSetAttribute(gemm_layer_kernel,
                         cudaFuncAttributeMaxDynamicSharedMemorySize,
                         (int)sizeof(GemmSM));

    embed_node_kernel<<<NN, 64>>>(x, node_W, node_b);
    embed_edge_kernel<<<EE, 64>>>(eattr, edge_W, edge_b);
    init_misc_kernel<<<(NN * HH + 255) / 256, 256>>>();

    for (int i = 0; i < LL; i++) {
        const float* Wi = conv_W + (size_t)i * 2 * HH * FPH;
        gemm_layer_kernel<<<dim3(HN_BLKS + P_BLKS, FPH / 128), 256,
                            sizeof(GemmSM)>>>(Wi);
        edge_kernel<<<EE / 8, 256>>>(conv_att + (size_t)i * NHD * 2 * HH,
                                     conv_g + i * NHD, conv_be + i * NHD, ei);
        int flags = (i > 0 ? 1 : 0) | (i == LL - 1 ? 2 : 0);
        node_update_kernel<<<(NN * HH + 255) / 256, 256>>>(conv_b + i * HH, flags);
    }

    score_kernel<<<NN, 64>>>(batch, gfeat, ga_W1, ga_b1, ga_W2, ga_b2);
    smax_kernel<<<(NN + 255) / 256, 256>>>(batch);
    expden_kernel<<<(NN + 255) / 256, 256>>>(batch);
    pool_kernel<<<NN, 64>>>(batch);
    out_kernel<<<GG, 64>>>(out_W1, out_b1, out_W2, out_b2, out);
}